// round 4
// baseline (speedup 1.0000x reference)
#include <cuda_runtime.h>
#include <cstdint>

// ---------------- problem dims ----------------
#define MDIM 8192
#define NDIM 2048
#define KDIM 2048
#define BM 128
#define BN 128
#define BK 64
#define NSTAGE 4
#define NCHUNK (KDIM / BK)   // 32

// smem: rows padded to 80 bytes (16B-aligned, conflict-free for ldmatrix)
#define ROWPAD 80
#define A_BYTES (BM * ROWPAD)            // 10240
#define B_BYTES (BN * ROWPAD)            // 10240
#define STAGE_BYTES (A_BYTES + B_BYTES)  // 20480
#define SMEM_TOTAL (NSTAGE * STAGE_BYTES) // 81920

// ---------------- device scratch ----------------
static __device__ float g_partial[1024];
static __device__ float g_scale;
static __device__ float g_gamma[MDIM];
static __device__ int8_t g_qw[(size_t)NDIM * KDIM];
static __device__ int8_t g_qx[(size_t)MDIM * KDIM];

// ---------------- helpers ----------------
__device__ __forceinline__ uint32_t smem_u32(const void* p) {
    uint32_t a;
    asm("{ .reg .u64 t; cvta.to.shared.u64 t, %1; cvt.u32.u64 %0, t; }"
        : "=r"(a) : "l"(p));
    return a;
}

__device__ __forceinline__ void ldgsts16(uint32_t s, const void* g) {
    asm volatile("cp.async.cg.shared.global [%0], [%1], 16;" :: "r"(s), "l"(g));
}
#define CP_COMMIT() asm volatile("cp.async.commit_group;" ::: "memory")
#define CP_WAIT2()  asm volatile("cp.async.wait_group 2;" ::: "memory")

__device__ __forceinline__ void ldsm_x4(uint32_t* r, uint32_t addr) {
    asm volatile("ldmatrix.sync.aligned.m8n8.x4.shared.b16 {%0,%1,%2,%3}, [%4];"
                 : "=r"(r[0]), "=r"(r[1]), "=r"(r[2]), "=r"(r[3]) : "r"(addr));
}

__device__ __forceinline__ void mma_s8(int* c, const uint32_t* a,
                                       uint32_t b0, uint32_t b1) {
    asm volatile(
        "mma.sync.aligned.m16n8k32.row.col.s32.s8.s8.s32 "
        "{%0,%1,%2,%3}, {%4,%5,%6,%7}, {%8,%9}, {%0,%1,%2,%3};"
        : "+r"(c[0]), "+r"(c[1]), "+r"(c[2]), "+r"(c[3])
        : "r"(a[0]), "r"(a[1]), "r"(a[2]), "r"(a[3]), "r"(b0), "r"(b1));
}

__device__ __forceinline__ uint32_t pack_s8(int a, int b, int c, int d) {
    return (a & 0xFF) | ((b & 0xFF) << 8) | ((c & 0xFF) << 16) | ((d & 0xFF) << 24);
}

// ---------------- quantization kernels ----------------

__global__ void k_wabs_partial(const float* __restrict__ w) {
    __shared__ float red[256];
    const int n = NDIM * KDIM;
    float s = 0.f;
    for (int i = blockIdx.x * 256 + threadIdx.x; i < n; i += 1024 * 256)
        s += fabsf(w[i]);
    red[threadIdx.x] = s;
    __syncthreads();
    for (int o = 128; o > 0; o >>= 1) {
        if (threadIdx.x < o) red[threadIdx.x] += red[threadIdx.x + o];
        __syncthreads();
    }
    if (threadIdx.x == 0) g_partial[blockIdx.x] = red[0];
}

__global__ void k_scale_final() {
    __shared__ float red[256];
    float s = 0.f;
    for (int i = threadIdx.x; i < 1024; i += 256) s += g_partial[i];
    red[threadIdx.x] = s;
    __syncthreads();
    for (int o = 128; o > 0; o >>= 1) {
        if (threadIdx.x < o) red[threadIdx.x] += red[threadIdx.x + o];
        __syncthreads();
    }
    if (threadIdx.x == 0)
        g_scale = fmaxf(red[0] / (float)(NDIM * KDIM), 1e-5f);
}

__global__ void k_quant_w(const float* __restrict__ w) {
    const float inv = 1.0f / g_scale;
    int i = blockIdx.x * blockDim.x + threadIdx.x;   // float4 index
    float4 v = reinterpret_cast<const float4*>(w)[i];
    int q0 = min(1, max(-1, __float2int_rn(v.x * inv)));
    int q1 = min(1, max(-1, __float2int_rn(v.y * inv)));
    int q2 = min(1, max(-1, __float2int_rn(v.z * inv)));
    int q3 = min(1, max(-1, __float2int_rn(v.w * inv)));
    reinterpret_cast<uint32_t*>(g_qw)[i] = pack_s8(q0, q1, q2, q3);
}

__global__ void k_quant_x(const float* __restrict__ x) {
    __shared__ float wmax[8];
    const int row = blockIdx.x;
    const int tid = threadIdx.x;
    const float4* xr = reinterpret_cast<const float4*>(x + (size_t)row * KDIM);
    float4 a = xr[tid];
    float4 b = xr[tid + 256];
    float m = fmaxf(fmaxf(fabsf(a.x), fabsf(a.y)), fmaxf(fabsf(a.z), fabsf(a.w)));
    m = fmaxf(m, fmaxf(fmaxf(fabsf(b.x), fabsf(b.y)), fmaxf(fabsf(b.z), fabsf(b.w))));
    for (int o = 16; o > 0; o >>= 1)
        m = fmaxf(m, __shfl_xor_sync(0xFFFFFFFFu, m, o));
    if ((tid & 31) == 0) wmax[tid >> 5] = m;
    __syncthreads();
    if (tid == 0) {
        float t = wmax[0];
        for (int i = 1; i < 8; i++) t = fmaxf(t, wmax[i]);
        t = fmaxf(t, 1e-5f);
        wmax[0] = t;
        g_gamma[row] = t;
    }
    __syncthreads();
    const float rq = 128.0f / wmax[0];
    uint32_t* qrow = reinterpret_cast<uint32_t*>(g_qx + (size_t)row * KDIM);
#define QV(v) min(127, max(-128, __float2int_rn((v) * rq)))
    qrow[tid]       = pack_s8(QV(a.x), QV(a.y), QV(a.z), QV(a.w));
    qrow[tid + 256] = pack_s8(QV(b.x), QV(b.y), QV(b.z), QV(b.w));
#undef QV
}

// ---------------- GEMM ----------------

__device__ __forceinline__ void load_stage(uint32_t sb, int stage, int kc,
                                           const int8_t* gA, const int8_t* gB,
                                           int tid) {
    uint32_t sA = sb + stage * STAGE_BYTES;
    const int8_t* pA = gA + kc * BK;
#pragma unroll
    for (int i = 0; i < 2; i++) {          // 128 rows x 64B = 512 chunks
        int u = tid + 256 * i;
        int row = u >> 2, seg = u & 3;
        ldgsts16(sA + row * ROWPAD + seg * 16, pA + (size_t)row * KDIM + seg * 16);
    }
    uint32_t sB = sA + A_BYTES;
    const int8_t* pB = gB + kc * BK;
#pragma unroll
    for (int i = 0; i < 2; i++) {
        int u = tid + 256 * i;
        int row = u >> 2, seg = u & 3;
        ldgsts16(sB + row * ROWPAD + seg * 16, pB + (size_t)row * KDIM + seg * 16);
    }
}

__global__ void __launch_bounds__(256, 1)
gemm_kernel(const float* __restrict__ bias, float* __restrict__ out) {
    extern __shared__ char smem[];
    const uint32_t sb = smem_u32(smem);
    const int tid = threadIdx.x;
    const int lane = tid & 31, wid = tid >> 5;
    const int warp_m = wid >> 2;       // 0..1 -> 64 rows each
    const int warp_n = wid & 3;        // 0..3 -> 32 cols each
    const int m0 = blockIdx.y * BM;
    const int n0 = blockIdx.x * BN;
    const int8_t* gA = g_qx + (size_t)m0 * KDIM;
    const int8_t* gB = g_qw + (size_t)n0 * KDIM;

    int acc[4][4][4];
#pragma unroll
    for (int i = 0; i < 4; i++)
#pragma unroll
        for (int j = 0; j < 4; j++)
#pragma unroll
            for (int k = 0; k < 4; k++) acc[i][j][k] = 0;

    // prologue: 3 stages in flight
#pragma unroll
    for (int s = 0; s < NSTAGE - 1; s++) {
        load_stage(sb, s, s, gA, gB, tid);
        CP_COMMIT();
    }

    const int row_lo = lane & 15;
    const int col16 = lane >> 4;

    for (int kc = 0; kc < NCHUNK; kc++) {
        CP_WAIT2();
        __syncthreads();
        const int pk = kc + NSTAGE - 1;
        if (pk < NCHUNK) load_stage(sb, pk & (NSTAGE - 1), pk, gA, gB, tid);
        CP_COMMIT();

        const int st = kc & (NSTAGE - 1);
        const uint32_t sA = sb + st * STAGE_BYTES;
        const uint32_t sB = sA + A_BYTES;
#pragma unroll
        for (int ks = 0; ks < 2; ks++) {
            const uint32_t koff = ks * 32 + col16 * 16;
            uint32_t afr[4][4];
#pragma unroll
            for (int fm = 0; fm < 4; fm++)
                ldsm_x4(afr[fm],
                        sA + (warp_m * 64 + fm * 16 + row_lo) * ROWPAD + koff);
            uint32_t bfr[2][4];
#pragma unroll
            for (int pr = 0; pr < 2; pr++)
                ldsm_x4(bfr[pr],
                        sB + (warp_n * 32 + pr * 16 + row_lo) * ROWPAD + koff);
#pragma unroll
            for (int fm = 0; fm < 4; fm++)
#pragma unroll
                for (int fn = 0; fn < 4; fn++) {
                    const int pr = fn >> 1, od = fn & 1;
                    mma_s8(acc[fm][fn], afr[fm], bfr[pr][od], bfr[pr][2 + od]);
                }
        }
    }

    // epilogue: out[r][c] = (acc + bias[c]) * scale * gamma[r] / 128
    const float sc = g_scale * (1.0f / 128.0f);
#pragma unroll
    for (int fm = 0; fm < 4; fm++) {
        const int r = m0 + warp_m * 64 + fm * 16 + (lane >> 2);
        const float cf0 = sc * g_gamma[r];
        const float cf1 = sc * g_gamma[r + 8];
#pragma unroll
        for (int fn = 0; fn < 4; fn++) {
            const int c = n0 + warp_n * 32 + fn * 8 + (lane & 3) * 2;
            const float b0 = bias[c], b1 = bias[c + 1];
            float2 v0, v1;
            v0.x = ((float)acc[fm][fn][0] + b0) * cf0;
            v0.y = ((float)acc[fm][fn][1] + b1) * cf0;
            v1.x = ((float)acc[fm][fn][2] + b0) * cf1;
            v1.y = ((float)acc[fm][fn][3] + b1) * cf1;
            *reinterpret_cast<float2*>(&out[(size_t)r * NDIM + c]) = v0;
            *reinterpret_cast<float2*>(&out[(size_t)(r + 8) * NDIM + c]) = v1;
        }
    }
}

// ---------------- launch ----------------
extern "C" void kernel_launch(void* const* d_in, const int* in_sizes, int n_in,
                              void* d_out, int out_size) {
    const float* x = (const float*)d_in[0];
    const float* w = (const float*)d_in[1];
    const float* bias = (const float*)d_in[2];
    float* out = (float*)d_out;

    cudaFuncSetAttribute(gemm_kernel, cudaFuncAttributeMaxDynamicSharedMemorySize,
                         SMEM_TOTAL);

    k_wabs_partial<<<1024, 256>>>(w);
    k_scale_final<<<1, 256>>>();
    k_quant_w<<<(NDIM * KDIM / 4) / 256, 256>>>(w);
    k_quant_x<<<MDIM, 256>>>(x);

    dim3 grid(NDIM / BN, MDIM / BM);
    gemm_kernel<<<grid, 256, SMEM_TOTAL>>>(bias, out);
}